// round 3
// baseline (speedup 1.0000x reference)
#include <cuda_runtime.h>
#include <math.h>

// Problem constants
#define Bb   32
#define Ss   1024
#define Hh   256
#define Pp   96
#define Ll   200
#define Oo   200
#define Ee   64
#define Mtot (Bb*Ss)   // 32768

// Scratch (static device allocations are the sanctioned workaround)
__device__ float g_h  [3u*Mtot*Ll];   // 78.6 MB
__device__ float g_hid[3u*Mtot*Ll];   // 78.6 MB
__device__ float g_qkv[3u*Mtot*Hh];   // 100.7 MB
__device__ float g_ctx[(unsigned)Mtot*Hh]; // 33.5 MB
__device__ float g_eco[Bb*Hh];

// ---------------------------------------------------------------------------
// eco_vec = eco_data @ W_eco + b_eco   [B,H]
// ---------------------------------------------------------------------------
__global__ void eco_kernel(const float* __restrict__ eco_data,
                           const float* __restrict__ W_eco,
                           const float* __restrict__ b_eco,
                           float* __restrict__ out)
{
    int b = blockIdx.x;
    int h = threadIdx.x;
    float acc = b_eco[h];
    #pragma unroll 8
    for (int e = 0; e < Ee; e++)
        acc = fmaf(eco_data[b*Ee + e], W_eco[e*Hh + h], acc);
    out[b*Hh + h] = acc;
}

// ---------------------------------------------------------------------------
// Generic tiled fp32 GEMM, C[M,N] = A[M,K] @ W[K,N] with fused epilogues.
// blockIdx.z = k-index (0..2) with per-operand strides.
// MODE 0: h-init   C = tanh(acc + timef[row]*Wt[col] + bias[col])
// MODE 1: hid      C = tanh(acc + bias[col])
// MODE 2: update   C += 0.25*(acc + bias[col])           (C is h)
// MODE 3: qkv      C = mask(row) * (acc + bias[col] + eco[b(row)][col])
// MODE 4: head     C = acc + bias[col]
// ---------------------------------------------------------------------------
template<int MODE>
__global__ __launch_bounds__(256)
void gemm_kernel(const float* __restrict__ A, const float* __restrict__ W,
                 float* __restrict__ C,
                 int M, int N, int K,
                 long aStride, long wStride, long cStride, int biasStride,
                 const float* __restrict__ bias,
                 const float* __restrict__ aux1,
                 const float* __restrict__ aux2, int aux2Stride)
{
    int kb = blockIdx.z;
    A += (long)kb * aStride;
    W += (long)kb * wStride;
    C += (long)kb * cStride;
    const float* bptr = bias + (long)kb * biasStride;
    const float* a2   = aux2 ? (aux2 + (long)kb * aux2Stride) : nullptr;

    __shared__ float As[64][17];   // +1 pad kills 2-way broadcast-group conflict
    __shared__ float Ws[16][64];

    int tid = threadIdx.x;
    int tx = tid & 15, ty = tid >> 4;
    int m0 = blockIdx.x * 64, n0 = blockIdx.y * 64;

    float acc[4][4] = {};

    for (int k0 = 0; k0 < K; k0 += 16) {
        #pragma unroll
        for (int i = 0; i < 4; i++) {
            int idx = tid + i*256;
            int r = idx >> 4, c = idx & 15;
            int gr = m0 + r, gc = k0 + c;
            As[r][c] = (gr < M && gc < K) ? A[(long)gr*K + gc] : 0.f;
        }
        #pragma unroll
        for (int i = 0; i < 4; i++) {
            int idx = tid + i*256;
            int r = idx >> 6, c = idx & 63;
            int gr = k0 + r, gc = n0 + c;
            Ws[r][c] = (gr < K && gc < N) ? W[(long)gr*N + gc] : 0.f;
        }
        __syncthreads();
        #pragma unroll
        for (int kk = 0; kk < 16; kk++) {
            float a[4];
            #pragma unroll
            for (int i = 0; i < 4; i++) a[i] = As[ty*4 + i][kk];
            float4 b4 = *(const float4*)&Ws[kk][tx*4];
            float bv[4] = {b4.x, b4.y, b4.z, b4.w};
            #pragma unroll
            for (int i = 0; i < 4; i++)
                #pragma unroll
                for (int j = 0; j < 4; j++)
                    acc[i][j] = fmaf(a[i], bv[j], acc[i][j]);
        }
        __syncthreads();
    }

    #pragma unroll
    for (int i = 0; i < 4; i++) {
        int row = m0 + ty*4 + i;
        if (row >= M) continue;
        #pragma unroll
        for (int j = 0; j < 4; j++) {
            int col = n0 + tx*4 + j;
            if (col >= N) continue;
            float v = acc[i][j];
            long o = (long)row*N + col;
            if (MODE == 0) {
                C[o] = tanhf(v + aux1[row]*a2[col] + bptr[col]);
            } else if (MODE == 1) {
                C[o] = tanhf(v + bptr[col]);
            } else if (MODE == 2) {
                C[o] = C[o] + 0.25f*(v + bptr[col]);
            } else if (MODE == 3) {
                v += bptr[col] + a2[(row >> 10)*Hh + col];  // eco_vec[b][col]
                float last = aux1[(long)row*Hh + (Hh-1)];   // tran_data[...,-1]
                C[o] = (last == 0.f) ? 0.f : v;
            } else {
                C[o] = v + bptr[col];
            }
        }
    }
}

// ---------------------------------------------------------------------------
// Attention: one CTA per (b, 32-row q-tile). Full score rows in SMEM.
//   smem: Sc[32][1024] + Qs[32][256] + Ks[256][65]  = 230400 B
// ---------------------------------------------------------------------------
__global__ __launch_bounds__(256)
void attn_kernel(const float* __restrict__ qkv, float* __restrict__ ctx)
{
    extern __shared__ float sm[];
    float* Sc = sm;                    // 32*1024
    float* Qs = Sc + 32*1024;          // 32*256
    float* Ks = Qs + 32*256;           // 256*65 (padded transpose)

    int b  = blockIdx.y;
    int q0 = blockIdx.x * 32;
    const float* Qg = qkv              + (long)b*Ss*Hh + (long)q0*Hh;
    const float* Kg = qkv + 1L*Mtot*Hh + (long)b*Ss*Hh;
    const float* Vg = qkv + 2L*Mtot*Hh + (long)b*Ss*Hh;

    int tid = threadIdx.x;
    for (int i = tid; i < 32*256; i += 256) Qs[i] = Qg[i];
    __syncthreads();

    int tx = tid & 15, ty = tid >> 4;
    const float scale = 0.0625f;   // 1/sqrt(256)

    // ---- Phase 1: scores = Q K^T * scale, key tiles of 64 ----
    for (int kt = 0; kt < 16; kt++) {
        // load K tile transposed: Ks[d*65 + key], d = tid
        #pragma unroll 8
        for (int it = 0; it < 64; it++)
            Ks[tid*65 + it] = Kg[(long)(kt*64 + it)*Hh + tid];
        __syncthreads();

        float acc[2][4] = {};
        int r0 = ty*2, r1 = r0 + 1;
        for (int d = 0; d < 256; d += 4) {
            float4 qa = *(const float4*)&Qs[r0*256 + d];
            float4 qb = *(const float4*)&Qs[r1*256 + d];
            float qav[4] = {qa.x, qa.y, qa.z, qa.w};
            float qbv[4] = {qb.x, qb.y, qb.z, qb.w};
            #pragma unroll
            for (int dd = 0; dd < 4; dd++) {
                #pragma unroll
                for (int j = 0; j < 4; j++) {
                    float kv = Ks[(d + dd)*65 + tx*4 + j];
                    acc[0][j] = fmaf(qav[dd], kv, acc[0][j]);
                    acc[1][j] = fmaf(qbv[dd], kv, acc[1][j]);
                }
            }
        }
        #pragma unroll
        for (int j = 0; j < 4; j++) {
            Sc[r0*1024 + kt*64 + tx*4 + j] = acc[0][j]*scale;
            Sc[r1*1024 + kt*64 + tx*4 + j] = acc[1][j]*scale;
        }
        __syncthreads();
    }

    // ---- Phase 2: softmax, one warp handles 4 rows ----
    int lane = tid & 31, w = tid >> 5;
    for (int rr = 0; rr < 4; rr++) {
        int r = w*4 + rr;
        float* row = Sc + r*1024;
        float mx = -1e30f;
        for (int j = lane; j < 1024; j += 32) mx = fmaxf(mx, row[j]);
        #pragma unroll
        for (int o = 16; o; o >>= 1) mx = fmaxf(mx, __shfl_xor_sync(0xffffffffu, mx, o));
        float s = 0.f;
        for (int j = lane; j < 1024; j += 32) {
            float e = __expf(row[j] - mx);
            row[j] = e;
            s += e;
        }
        #pragma unroll
        for (int o = 16; o; o >>= 1) s += __shfl_xor_sync(0xffffffffu, s, o);
        float inv = 1.f / s;
        for (int j = lane; j < 1024; j += 32) row[j] *= inv;
    }
    __syncthreads();

    // ---- Phase 3: ctx = P @ V; thread owns one H column, 32 q-rows ----
    float acc2[32];
    #pragma unroll
    for (int r = 0; r < 32; r++) acc2[r] = 0.f;
    for (int j = 0; j < 1024; j += 4) {
        float v0 = Vg[(long)(j+0)*Hh + tid];
        float v1 = Vg[(long)(j+1)*Hh + tid];
        float v2 = Vg[(long)(j+2)*Hh + tid];
        float v3 = Vg[(long)(j+3)*Hh + tid];
        #pragma unroll
        for (int r = 0; r < 32; r++) {
            float4 p = *(const float4*)&Sc[r*1024 + j];
            acc2[r] = fmaf(p.x, v0, fmaf(p.y, v1, fmaf(p.z, v2, fmaf(p.w, v3, acc2[r]))));
        }
    }
    #pragma unroll
    for (int r = 0; r < 32; r++)
        ctx[(long)b*Ss*Hh + (long)(q0 + r)*Hh + tid] = acc2[r];
}

// ---------------------------------------------------------------------------
extern "C" void kernel_launch(void* const* d_in, const int* in_sizes, int n_in,
                              void* d_out, int out_size)
{
    const float* eco_data = (const float*)d_in[0];
    const float* tran     = (const float*)d_in[1];
    // d_in[2] tran_data_label: unused by reference
    const float* time_x   = (const float*)d_in[3];
    // d_in[4] time_y: dead (concat+slice == time_x), d_in[5] alpha: unused
    const float* W_eco = (const float*)d_in[6];
    const float* b_eco = (const float*)d_in[7];
    const float* W_in  = (const float*)d_in[8];
    const float* W_t   = (const float*)d_in[9];
    const float* b_in  = (const float*)d_in[10];
    const float* W_f1  = (const float*)d_in[11];
    const float* b_f1  = (const float*)d_in[12];
    const float* W_f2  = (const float*)d_in[13];
    const float* b_f2  = (const float*)d_in[14];
    const float* W_out = (const float*)d_in[15];
    const float* b_out = (const float*)d_in[16];
    const float* W_lin = (const float*)d_in[17];
    const float* b_lin = (const float*)d_in[18];
    float* out = (float*)d_out;

    float *h, *hid, *qkv, *ctx, *eco;
    cudaGetSymbolAddress((void**)&h,   g_h);
    cudaGetSymbolAddress((void**)&hid, g_hid);
    cudaGetSymbolAddress((void**)&qkv, g_qkv);
    cudaGetSymbolAddress((void**)&ctx, g_ctx);
    cudaGetSymbolAddress((void**)&eco, g_eco);

    dim3 blk(256);

    // eco encoder
    eco_kernel<<<Bb, Hh>>>(eco_data, W_eco, b_eco, eco);

    // h = tanh(tran @ W_in + time_x * W_t + b_in)   [3][M][L]
    gemm_kernel<0><<<dim3(Mtot/64, (Ll+63)/64, 3), blk>>>(
        tran, W_in, h, Mtot, Ll, Hh,
        0L, (long)Hh*Ll, (long)Mtot*Ll, Ll, b_in, time_x, W_t, Ll);

    // 4 Euler steps
    for (int it = 0; it < 4; it++) {
        gemm_kernel<1><<<dim3(Mtot/64, (Oo+63)/64, 3), blk>>>(
            h, W_f1, hid, Mtot, Oo, Ll,
            (long)Mtot*Ll, (long)Ll*Oo, (long)Mtot*Oo, Oo, b_f1, nullptr, nullptr, 0);
        gemm_kernel<2><<<dim3(Mtot/64, (Ll+63)/64, 3), blk>>>(
            hid, W_f2, h, Mtot, Ll, Oo,
            (long)Mtot*Oo, (long)Oo*Ll, (long)Mtot*Ll, Ll, b_f2, nullptr, nullptr, 0);
    }

    // qkv = mask * (h @ W_out + b_out + eco)    [3][M][H]
    gemm_kernel<3><<<dim3(Mtot/64, Hh/64, 3), blk>>>(
        h, W_out, qkv, Mtot, Hh, Ll,
        (long)Mtot*Ll, (long)Ll*Hh, (long)Mtot*Hh, Hh, b_out, tran, eco, 0);

    // attention
    size_t smem = (size_t)(32*1024 + 32*256 + 256*65) * sizeof(float); // 230400
    cudaFuncSetAttribute(attn_kernel, cudaFuncAttributeMaxDynamicSharedMemorySize, (int)smem);
    attn_kernel<<<dim3(Ss/32, Bb), blk, smem>>>(qkv, ctx);

    // out = ctx @ W_lin + b_lin   [M][P]
    gemm_kernel<4><<<dim3(Mtot/64, (Pp+63)/64, 1), blk>>>(
        ctx, W_lin, out, Mtot, Pp, Hh,
        0L, 0L, 0L, 0, b_lin, nullptr, nullptr, 0);
}